// round 1
// baseline (speedup 1.0000x reference)
#include <cuda_runtime.h>

// Problem constants
#define SS   128      // MSA depth S
#define NRES 256      // N residues
#define DD   64       // msa dim
#define HH_  32       // proj dim H
#define PP   64       // output dim P
#define M_TOT 8192    // N*H
#define KK2  1024     // H*H

// Device scratch (allocation-free rule: __device__ globals)
__device__ float g_A[SS * M_TOT];                 // [s][i*32+h], (xWa+ba)*mask/denom[i]   4 MB
__device__ float g_B[SS * M_TOT];                 // [s][j*32+k], (xWb+bb)*mask            4 MB
__device__ float g_outer[(size_t)65536 * KK2];    // [(i*256+j)][h*32+k]                 256 MB
__device__ float g_invden[NRES];

// ---------------- f32x2 packed helpers (sm_103a FFMA2 path) ----------------
__device__ __forceinline__ unsigned long long pack2(float lo, float hi) {
    unsigned long long r;
    asm("mov.b64 %0, {%1, %2};" : "=l"(r) : "f"(lo), "f"(hi));
    return r;
}
__device__ __forceinline__ void unpack2(unsigned long long v, float& lo, float& hi) {
    asm("mov.b64 {%0, %1}, %2;" : "=f"(lo), "=f"(hi) : "l"(v));
}
__device__ __forceinline__ void ffma2(unsigned long long& d, unsigned long long a, unsigned long long b) {
    asm("fma.rn.f32x2 %0, %1, %2, %0;" : "+l"(d) : "l"(a), "l"(b));
}

// ---------------- denom: denom[i] = max(sum_s mask[s,i], 1) ----------------
__global__ void k_denom(const float* __restrict__ mask) {
    int i = threadIdx.x;  // 256 threads
    float s = 0.f;
    #pragma unroll 8
    for (int t = 0; t < SS; ++t) s += mask[t * NRES + i];
    g_invden[i] = 1.0f / fmaxf(s, 1.0f);
}

// ---------------- prep: LN + dual projection + mask + denom fold ----------------
// 256 threads = 8 warps, one row (s,i) per warp.
__global__ void __launch_bounds__(256) k_prep(
    const float* __restrict__ x, const float* __restrict__ mask,
    const float* __restrict__ gamma, const float* __restrict__ beta,
    const float* __restrict__ Wa, const float* __restrict__ ba,
    const float* __restrict__ Wb, const float* __restrict__ bb)
{
    __shared__ float sx[8][64];
    int warp = threadIdx.x >> 5, lane = threadIdx.x & 31;
    int row = blockIdx.x * 8 + warp;          // row = s*256 + i
    const float* xr = x + (size_t)row * DD;

    float v0 = xr[lane], v1 = xr[lane + 32];
    float sum = v0 + v1;
    #pragma unroll
    for (int o = 16; o; o >>= 1) sum += __shfl_xor_sync(~0u, sum, o);
    float mu = sum * (1.0f / 64.0f);
    float d0 = v0 - mu, d1 = v1 - mu;
    float vs = d0 * d0 + d1 * d1;
    #pragma unroll
    for (int o = 16; o; o >>= 1) vs += __shfl_xor_sync(~0u, vs, o);
    float rstd = rsqrtf(vs * (1.0f / 64.0f) + 1e-5f);
    sx[warp][lane]      = d0 * rstd * gamma[lane]      + beta[lane];
    sx[warp][lane + 32] = d1 * rstd * gamma[lane + 32] + beta[lane + 32];
    __syncwarp();

    int s = row >> 8, i = row & 255;
    float m = mask[s * NRES + i];
    float a = ba[lane], b = bb[lane];
    #pragma unroll
    for (int d = 0; d < 64; ++d) {
        float xv = sx[warp][d];
        a = fmaf(xv, Wa[d * HH_ + lane], a);
        b = fmaf(xv, Wb[d * HH_ + lane], b);
    }
    a *= m * g_invden[i];
    b *= m;
    g_A[s * M_TOT + i * HH_ + lane] = a;
    g_B[s * M_TOT + i * HH_ + lane] = b;
}

// ---------------- GEMM1: C[m,n] = sum_s A[s,m]*B[s,n], tile 128x128, K=128 ----------------
// Writes directly into g_outer in (i*256+j, h*32+k) permuted layout.
__global__ void __launch_bounds__(256) k_gemm1() {
    extern __shared__ float sm[];              // 128 KB dynamic
    float* sA = sm;                            // [k][m] 128x128
    float* sB = sm + 128 * 128;                // [k][n] 128x128
    int tid = threadIdx.x;
    int bm = blockIdx.x, bn = blockIdx.y;

    const float* gA = g_A + bm * 128;
    const float* gB = g_B + bn * 128;
    #pragma unroll
    for (int it = 0; it < 16; ++it) {
        int idx = it * 256 + tid;              // float4 index over 128x32
        int k = idx >> 5, c4 = (idx & 31) << 2;
        *(float4*)&sA[k * 128 + c4] = *(const float4*)&gA[(size_t)k * M_TOT + c4];
        *(float4*)&sB[k * 128 + c4] = *(const float4*)&gB[(size_t)k * M_TOT + c4];
    }
    __syncthreads();

    int tx = tid & 15, ty = tid >> 4;
    unsigned long long acc[8][4];
    #pragma unroll
    for (int i = 0; i < 8; ++i)
        #pragma unroll
        for (int j = 0; j < 4; ++j) acc[i][j] = 0ull;

    #pragma unroll 4
    for (int k = 0; k < 128; ++k) {
        float4 a0 = *(float4*)&sA[k * 128 + ty * 8];
        float4 a1 = *(float4*)&sA[k * 128 + ty * 8 + 4];
        float4 b0 = *(float4*)&sB[k * 128 + tx * 8];
        float4 b1 = *(float4*)&sB[k * 128 + tx * 8 + 4];
        unsigned long long bp[4] = { pack2(b0.x, b0.y), pack2(b0.z, b0.w),
                                     pack2(b1.x, b1.y), pack2(b1.z, b1.w) };
        float av[8] = { a0.x, a0.y, a0.z, a0.w, a1.x, a1.y, a1.z, a1.w };
        #pragma unroll
        for (int i = 0; i < 8; ++i) {
            unsigned long long a2 = pack2(av[i], av[i]);
            #pragma unroll
            for (int j = 0; j < 4; ++j) ffma2(acc[i][j], a2, bp[j]);
        }
    }

    // Permuted store: (m,n) -> row r=(m/32)*256+(n/32), col c=(m%32)*32+(n%32)
    #pragma unroll
    for (int i = 0; i < 8; ++i) {
        int m = bm * 128 + ty * 8 + i;
        int ii = m >> 5, h = m & 31;
        #pragma unroll
        for (int j = 0; j < 4; ++j) {
            int n = bn * 128 + tx * 8 + j * 2;   // pair (n, n+1) stays within one 32-block
            int jj = n >> 5, kk = n & 31;
            size_t idx = (size_t)(ii * 256 + jj) * KK2 + h * 32 + kk;
            *(unsigned long long*)&g_outer[idx] = acc[i][j];   // float2 bits
        }
    }
}

// ---------------- GEMM2: out[r,p] = sum_c outer[r,c]*Wo[c,p] + bo[p] ----------------
// M=65536, N=64, K=1024. BM=128, BN=64, BK=32, double-buffered via register prefetch.
__global__ void __launch_bounds__(256) k_gemm2(
    const float* __restrict__ Wo, const float* __restrict__ bo, float* __restrict__ out)
{
    __shared__ float sA[2][128 * 32];   // [r][k]  16 KB each
    __shared__ float sW[2][32 * 64];    // [k][p]   8 KB each   (total 48 KB)
    int tid = threadIdx.x;
    int tx = tid & 15, ty = tid >> 4;
    const float* gO = g_outer + (size_t)blockIdx.x * 128 * KK2;

    // chunk 0
    #pragma unroll
    for (int it = 0; it < 4; ++it) {
        int idx = it * 256 + tid; int r = idx >> 3, c4 = (idx & 7) << 2;
        *(float4*)&sA[0][r * 32 + c4] = *(const float4*)&gO[(size_t)r * KK2 + c4];
    }
    #pragma unroll
    for (int it = 0; it < 2; ++it) {
        int idx = it * 256 + tid; int k = idx >> 4, p4 = (idx & 15) << 2;
        *(float4*)&sW[0][k * 64 + p4] = *(const float4*)&Wo[(size_t)k * 64 + p4];
    }
    __syncthreads();

    unsigned long long acc[8][2];
    #pragma unroll
    for (int i = 0; i < 8; ++i) { acc[i][0] = 0ull; acc[i][1] = 0ull; }

    float4 pfA[4]; float4 pfW[2];
    for (int ch = 0; ch < 32; ++ch) {
        int cur = ch & 1;
        if (ch < 31) {
            int kb = (ch + 1) * 32;
            #pragma unroll
            for (int it = 0; it < 4; ++it) {
                int idx = it * 256 + tid; int r = idx >> 3, c4 = (idx & 7) << 2;
                pfA[it] = *(const float4*)&gO[(size_t)r * KK2 + kb + c4];
            }
            #pragma unroll
            for (int it = 0; it < 2; ++it) {
                int idx = it * 256 + tid; int k = idx >> 4, p4 = (idx & 15) << 2;
                pfW[it] = *(const float4*)&Wo[(size_t)(kb + k) * 64 + p4];
            }
        }
        #pragma unroll
        for (int kk = 0; kk < 32; ++kk) {
            float4 w0 = *(float4*)&sW[cur][kk * 64 + tx * 4];
            unsigned long long w01 = pack2(w0.x, w0.y), w23 = pack2(w0.z, w0.w);
            #pragma unroll
            for (int i = 0; i < 8; ++i) {
                float av = sA[cur][(ty * 8 + i) * 32 + kk];   // 2-way broadcast
                unsigned long long a2 = pack2(av, av);
                ffma2(acc[i][0], a2, w01);
                ffma2(acc[i][1], a2, w23);
            }
        }
        if (ch < 31) {
            int nxt = cur ^ 1;
            #pragma unroll
            for (int it = 0; it < 4; ++it) {
                int idx = it * 256 + tid; int r = idx >> 3, c4 = (idx & 7) << 2;
                *(float4*)&sA[nxt][r * 32 + c4] = pfA[it];
            }
            #pragma unroll
            for (int it = 0; it < 2; ++it) {
                int idx = it * 256 + tid; int k = idx >> 4, p4 = (idx & 15) << 2;
                *(float4*)&sW[nxt][k * 64 + p4] = pfW[it];
            }
        }
        __syncthreads();
    }

    #pragma unroll
    for (int i = 0; i < 8; ++i) {
        size_t r = (size_t)blockIdx.x * 128 + ty * 8 + i;
        #pragma unroll
        for (int j = 0; j < 2; ++j) {
            float lo, hi; unpack2(acc[i][j], lo, hi);
            int p = tx * 4 + j * 2;
            float2 v = make_float2(lo + bo[p], hi + bo[p + 1]);
            *(float2*)&out[r * 64 + p] = v;
        }
    }
}

extern "C" void kernel_launch(void* const* d_in, const int* in_sizes, int n_in,
                              void* d_out, int out_size) {
    const float* msa   = (const float*)d_in[0];
    const float* mask  = (const float*)d_in[1];
    const float* gamma = (const float*)d_in[2];
    const float* beta  = (const float*)d_in[3];
    const float* Wa    = (const float*)d_in[4];
    const float* ba    = (const float*)d_in[5];
    const float* Wb    = (const float*)d_in[6];
    const float* bb    = (const float*)d_in[7];
    const float* Wo    = (const float*)d_in[8];
    const float* bo    = (const float*)d_in[9];
    float* out = (float*)d_out;

    cudaFuncSetAttribute(k_gemm1, cudaFuncAttributeMaxDynamicSharedMemorySize, 131072);

    k_denom<<<1, 256>>>(mask);
    k_prep<<<4096, 256>>>(msa, mask, gamma, beta, Wa, ba, Wb, bb);
    k_gemm1<<<dim3(64, 64), 256, 131072>>>();
    k_gemm2<<<512, 256>>>(Wo, bo, out);
}